// round 11
// baseline (speedup 1.0000x reference)
#include <cuda_runtime.h>
#include <cuda_fp16.h>
#include <cstdint>

#define R_TOT   48
#define N_NODES 1000
#define RN      48000          // R_TOT * N_NODES
#define E_IN    12000
#define F_DIM   64
#define HC      256            // H * C
#define H_HEADS 4
#define E_MAX   (E_IN + N_NODES)

// ---------------- scratch (static device globals; no allocation) -------------
// h stored as fp16, row-major [RN][256] halves (viewed as [RN][32] uint4 by k_agg)
__device__ uint4  g_hv[(size_t)RN * 32];
__device__ float  g_asrc[RN * H_HEADS];
__device__ float  g_adst[RN * H_HEADS];
__device__ float4 g_Wf[8 * 32 * 32];    // pre-split W fragments: [kstep][ntile][lane]
__device__ float4 g_ew[(size_t)R_TOT * E_MAX];  // per-(r,edge) head weights (10 MB)
__device__ int    g_cnt[N_NODES];       // zero-init (BSS); re-zeroed by k_ss
__device__ int    g_rowptr[N_NODES + 1];
__device__ int    g_cursor[N_NODES];
__device__ int    g_csrc[E_MAX];
__device__ int    g_cdst[E_MAX];
__device__ int    g_is32;

// ---------------- packed helpers ----------------------------------------------
union F2U { unsigned long long u; float2 f; };
__device__ __forceinline__ unsigned long long fma2(unsigned long long a,
                                                   unsigned long long b,
                                                   unsigned long long c) {
    unsigned long long d;
    asm("fma.rn.f32x2 %0, %1, %2, %3;" : "=l"(d) : "l"(a), "l"(b), "l"(c));
    return d;
}

__device__ __forceinline__ unsigned tf32_rna(float v) {
    unsigned r;
    asm("cvt.rna.tf32.f32 %0, %1;" : "=r"(r) : "f"(v));
    return r;
}

#define MMA_TF32(d, a, b0, b1)                                                  \
    asm volatile("mma.sync.aligned.m16n8k8.row.col.f32.tf32.tf32.f32 "          \
                 "{%0,%1,%2,%3}, {%4,%5,%6,%7}, {%8,%9}, {%0,%1,%2,%3};"        \
                 : "+f"((d)[0]), "+f"((d)[1]), "+f"((d)[2]), "+f"((d)[3])       \
                 : "r"((a)[0]), "r"((a)[1]), "r"((a)[2]), "r"((a)[3]),          \
                   "r"(b0), "r"(b1))

// ---------------- CSR build + W split -----------------------------------------
// Original self-loops dropped (reference masks them to -inf => exp == 0 exactly);
// one added self-loop per node occupies the first CSR slot deterministically.

__device__ __forceinline__ int detect_is32_warp(const int* e32, int lane) {
    int f = (e32[2 * (lane * 375) + 1] != 0);
    unsigned b = __ballot_sync(0xffffffffu, f);
    return b != 0;
}

// Fused: blocks [0,32) pre-split W into mma B-fragment order; blocks [32,79)
// count edge in-degrees.
__global__ __launch_bounds__(256) void k_cw(const void* __restrict__ ei,
                                            const float* __restrict__ W) {
    int t = threadIdx.x;
    if (blockIdx.x < 32) {
        int i = blockIdx.x * 256 + t;            // 0..8191
        int lane = i & 31, ntg = (i >> 5) & 31, ks = i >> 10;
        int t4 = lane & 3, g = lane >> 2;
        int col = ntg * 8 + g;
        float b0 = W[(ks * 8 + t4) * HC + col];
        float b1 = W[(ks * 8 + t4 + 4) * HC + col];
        unsigned b0h = tf32_rna(b0), b1h = tf32_rna(b1);
        unsigned b0l = tf32_rna(b0 - __uint_as_float(b0h));
        unsigned b1l = tf32_rna(b1 - __uint_as_float(b1h));
        g_Wf[i] = make_float4(__uint_as_float(b0h), __uint_as_float(b1h),
                              __uint_as_float(b0l), __uint_as_float(b1l));
        return;
    }
    __shared__ int s_is32;
    const int* e32 = (const int*)ei;
    const long long* e64 = (const long long*)ei;
    if (t < 32) {
        int is32 = detect_is32_warp(e32, t);
        if (t == 0) {
            s_is32 = is32;
            if (blockIdx.x == 32) g_is32 = is32;
        }
    }
    __syncthreads();
    int is32 = s_is32;
    int e = (blockIdx.x - 32) * 256 + t;
    if (e < E_IN) {
        int s = is32 ? e32[e] : (int)e64[e];
        int d = is32 ? e32[E_IN + e] : (int)e64[E_IN + e];
        if (s != d) atomicAdd(&g_cnt[d], 1);
    }
}

// Fused scan + scatter (one block, 1024 threads); also records edge dst.
__global__ __launch_bounds__(1024) void k_ss(const void* __restrict__ ei) {
    __shared__ int s_wsum[32];
    int t = threadIdx.x, lane = t & 31, wid = t >> 5;
    int v = (t < N_NODES) ? (g_cnt[t] + 1) : 0;      // +1 = added self-loop
    int x = v;
#pragma unroll
    for (int o = 1; o < 32; o <<= 1) {
        int y = __shfl_up_sync(0xffffffffu, x, o);
        if (lane >= o) x += y;
    }
    if (lane == 31) s_wsum[wid] = x;
    __syncthreads();
    if (wid == 0) {
        int w = s_wsum[lane];
#pragma unroll
        for (int o = 1; o < 32; o <<= 1) {
            int y = __shfl_up_sync(0xffffffffu, w, o);
            if (lane >= o) w += y;
        }
        s_wsum[lane] = w;
    }
    __syncthreads();
    int incl = x + (wid ? s_wsum[wid - 1] : 0);
    int excl = incl - v;
    if (t < N_NODES) {
        g_rowptr[t] = excl;
        g_csrc[excl] = t;                // self-loop first, deterministic
        g_cdst[excl] = t;
        g_cursor[t] = excl + 1;
        g_cnt[t] = 0;                    // reset for next graph replay
    }
    if (t == N_NODES - 1) g_rowptr[N_NODES] = incl;

    const int* e32 = (const int*)ei;
    const long long* e64 = (const long long*)ei;
    int is32 = g_is32;
    int sv[12], dv[12];
    if (is32) {
#pragma unroll
        for (int k = 0; k < 12; k++) {
            int e = t + k * 1024;
            sv[k] = (e < E_IN) ? e32[e] : 0;
            dv[k] = (e < E_IN) ? e32[E_IN + e] : 0;
        }
    } else {
#pragma unroll
        for (int k = 0; k < 12; k++) {
            int e = t + k * 1024;
            sv[k] = (e < E_IN) ? (int)e64[e] : 0;
            dv[k] = (e < E_IN) ? (int)e64[E_IN + e] : 0;
        }
    }
    __syncthreads();
#pragma unroll
    for (int k = 0; k < 12; k++) {
        int e = t + k * 1024;
        if (e < E_IN && sv[k] != dv[k]) {
            int p = atomicAdd(&g_cursor[dv[k]], 1);
            g_csrc[p] = sv[k];
            g_cdst[p] = dv[k];
        }
    }
}

// ---------------- projection GEMM (tensor cores, 3xTF32) + logits -------------
// R7-proposal variant (best measured total): scalar x loads + in-loop split.
// Block: 8 warps = 2 row-groups x 4 col-groups; warp = 32 rows x 64 cols
// (one head per warp). D = Xhi*Whi + Xhi*Wlo + Xlo*Whi.
__global__ __launch_bounds__(256, 2) void k_gemm(const float* __restrict__ x,
                                                 const float* __restrict__ attS,
                                                 const float* __restrict__ attD) {
    __shared__ float sAS[HC], sAD[HC];
    int t = threadIdx.x, warp = t >> 5, lane = t & 31;
    int g = lane >> 2, t4 = lane & 3;
    int mg = warp >> 2, ng = warp & 3;
    int rbase = blockIdx.x * 64 + mg * 32;

    if (t < HC) { sAS[t] = attS[t]; sAD[t] = attD[t]; }
    __syncthreads();

    float acc[2][8][4];
#pragma unroll
    for (int mt = 0; mt < 2; mt++)
#pragma unroll
        for (int nt = 0; nt < 8; nt++)
#pragma unroll
            for (int j = 0; j < 4; j++) acc[mt][nt][j] = 0.f;

#pragma unroll
    for (int ks = 0; ks < 8; ks++) {
        unsigned ah[2][4], al[2][4];
#pragma unroll
        for (int mt = 0; mt < 2; mt++) {
            const float* xp = x + (size_t)(rbase + mt * 16 + g) * F_DIM + ks * 8 + t4;
            float v0 = xp[0];
            float v1 = xp[8 * F_DIM];
            float v2 = xp[4];
            float v3 = xp[8 * F_DIM + 4];
            ah[mt][0] = tf32_rna(v0); al[mt][0] = tf32_rna(v0 - __uint_as_float(ah[mt][0]));
            ah[mt][1] = tf32_rna(v1); al[mt][1] = tf32_rna(v1 - __uint_as_float(ah[mt][1]));
            ah[mt][2] = tf32_rna(v2); al[mt][2] = tf32_rna(v2 - __uint_as_float(ah[mt][2]));
            ah[mt][3] = tf32_rna(v3); al[mt][3] = tf32_rna(v3 - __uint_as_float(ah[mt][3]));
        }
#pragma unroll
        for (int nt = 0; nt < 8; nt++) {
            float4 b = g_Wf[((size_t)ks * 32 + ng * 8 + nt) * 32 + lane];
            unsigned b0h = __float_as_uint(b.x), b1h = __float_as_uint(b.y);
            unsigned b0l = __float_as_uint(b.z), b1l = __float_as_uint(b.w);
#pragma unroll
            for (int mt = 0; mt < 2; mt++) {
                MMA_TF32(acc[mt][nt], ah[mt], b0h, b1h);
                MMA_TF32(acc[mt][nt], ah[mt], b0l, b1l);
                MMA_TF32(acc[mt][nt], al[mt], b0h, b1h);
            }
        }
    }

    int head = ng, n0 = ng * 64;
    __half* hbase = (__half*)g_hv;
#pragma unroll
    for (int mt = 0; mt < 2; mt++) {
        int row0 = rbase + mt * 16 + g;
        float as0 = 0.f, ad0 = 0.f, as1 = 0.f, ad1 = 0.f;
#pragma unroll
        for (int nt = 0; nt < 8; nt++) {
            int c = n0 + nt * 8 + 2 * t4;
            float* a = acc[mt][nt];
            as0 += a[0] * sAS[c] + a[1] * sAS[c + 1];
            ad0 += a[0] * sAD[c] + a[1] * sAD[c + 1];
            as1 += a[2] * sAS[c] + a[3] * sAS[c + 1];
            ad1 += a[2] * sAD[c] + a[3] * sAD[c + 1];
            *(__half2*)(hbase + (size_t)row0 * HC + c)       = __floats2half2_rn(a[0], a[1]);
            *(__half2*)(hbase + (size_t)(row0 + 8) * HC + c) = __floats2half2_rn(a[2], a[3]);
        }
        as0 += __shfl_xor_sync(0xffffffffu, as0, 1); as0 += __shfl_xor_sync(0xffffffffu, as0, 2);
        ad0 += __shfl_xor_sync(0xffffffffu, ad0, 1); ad0 += __shfl_xor_sync(0xffffffffu, ad0, 2);
        as1 += __shfl_xor_sync(0xffffffffu, as1, 1); as1 += __shfl_xor_sync(0xffffffffu, as1, 2);
        ad1 += __shfl_xor_sync(0xffffffffu, ad1, 1); ad1 += __shfl_xor_sync(0xffffffffu, ad1, 2);
        if (t4 == 0) {
            g_asrc[row0 * 4 + head] = as0;
            g_adst[row0 * 4 + head] = ad0;
            g_asrc[(row0 + 8) * 4 + head] = as1;
            g_adst[(row0 + 8) * 4 + head] = ad1;
        }
    }
}

// ---------------- edge-weight precompute --------------------------------------
// One thread per (r, csr-slot): all 4 head weights (leaky+exp) -> g_ew.
// Identical math to the previous in-agg computation (no max-shift; clamp 80).
__global__ __launch_bounds__(256) void k_ew() {
    int idx = blockIdx.x * 256 + threadIdx.x;
    int r = idx / E_MAX, k = idx - r * E_MAX;
    if (r >= R_TOT) return;
    if (k >= g_rowptr[N_NODES]) return;
    int s = g_csrc[k], d = g_cdst[k];
    int rb = r * N_NODES;
    float4 as4 = *(const float4*)(g_asrc + (size_t)(rb + s) * 4);
    float4 ad4 = *(const float4*)(g_adst + (size_t)(rb + d) * 4);
    float e0 = as4.x + ad4.x, e1 = as4.y + ad4.y;
    float e2 = as4.z + ad4.z, e3 = as4.w + ad4.w;
    e0 = (e0 > 0.f) ? e0 : 0.2f * e0;
    e1 = (e1 > 0.f) ? e1 : 0.2f * e1;
    e2 = (e2 > 0.f) ? e2 : 0.2f * e2;
    e3 = (e3 > 0.f) ? e3 : 0.2f * e3;
    g_ew[(size_t)r * E_MAX + k] = make_float4(
        __expf(fminf(e0, 80.f)), __expf(fminf(e1, 80.f)),
        __expf(fminf(e2, 80.f)), __expf(fminf(e3, 80.f)));
}

// ---------------- softmax aggregation (single pass, one warp per (r, dst)) ----
// Hot loop: broadcast csrc + 4B weight load + 16B h load + 4 packed fma2.
__global__ __launch_bounds__(256) void k_agg(const float* __restrict__ bias,
                                             float* __restrict__ out) {
    int gw = (blockIdx.x * blockDim.x + threadIdx.x) >> 5;
    int lane = threadIdx.x & 31;
    if (gw >= RN) return;
    int r = gw / N_NODES, i = gw - r * N_NODES;
    int head = lane >> 3;
    int start = g_rowptr[i], end = g_rowptr[i + 1];
    int rbase = r * N_NODES;
    const float* ewp = (const float*)(g_ew + (size_t)r * E_MAX);
    const uint4* hvp = g_hv + (size_t)rbase * 32 + lane;

    float den = 1e-16f;
    unsigned long long acc[4] = {0ULL, 0ULL, 0ULL, 0ULL};

#pragma unroll 2
    for (int k = start; k < end; k++) {
        int s = g_csrc[k];                       // broadcast LDG
        float w = ewp[k * 4 + head];             // 4 distinct addrs/warp
        den += w;
        F2U wp; wp.f = make_float2(w, w);
        uint4 u = hvp[(size_t)s * 32];           // 16B/lane, 512B/warp
        F2U f0, f1, f2, f3;
        f0.f = __half22float2(*reinterpret_cast<__half2*>(&u.x));
        f1.f = __half22float2(*reinterpret_cast<__half2*>(&u.y));
        f2.f = __half22float2(*reinterpret_cast<__half2*>(&u.z));
        f3.f = __half22float2(*reinterpret_cast<__half2*>(&u.w));
        acc[0] = fma2(wp.u, f0.u, acc[0]);
        acc[1] = fma2(wp.u, f1.u, acc[1]);
        acc[2] = fma2(wp.u, f2.u, acc[2]);
        acc[3] = fma2(wp.u, f3.u, acc[3]);
    }

    float inv = 1.0f / den;
    float a[8];
#pragma unroll
    for (int j = 0; j < 4; j++) {
        F2U u; u.u = acc[j];
        a[2 * j] = u.f.x * inv; a[2 * j + 1] = u.f.y * inv;
    }

    // head mean: lanes l, l^8, l^16, l^24 hold same channel, different heads
#pragma unroll
    for (int k = 0; k < 8; k++) {
        a[k] += __shfl_xor_sync(0xffffffffu, a[k], 8);
        a[k] += __shfl_xor_sync(0xffffffffu, a[k], 16);
    }

    if (lane < 8) {
        const float4* bp = (const float4*)bias;
        float4 b0 = bp[lane * 2], b1 = bp[lane * 2 + 1];
        float4 o0 = make_float4(0.25f * a[0] + b0.x, 0.25f * a[1] + b0.y,
                                0.25f * a[2] + b0.z, 0.25f * a[3] + b0.w);
        float4 o1 = make_float4(0.25f * a[4] + b1.x, 0.25f * a[5] + b1.y,
                                0.25f * a[6] + b1.z, 0.25f * a[7] + b1.w);
        float4* op = (float4*)(out + (size_t)(rbase + i) * 64 + lane * 8);
        op[0] = o0;
        op[1] = o1;
    }
}

// ---------------- launch ------------------------------------------------------
extern "C" void kernel_launch(void* const* d_in, const int* in_sizes, int n_in,
                              void* d_out, int out_size) {
    const float* x    = (const float*)d_in[0];
    const void*  ei   = d_in[1];
    const float* W    = (const float*)d_in[2];
    const float* attS = (const float*)d_in[3];
    const float* attD = (const float*)d_in[4];
    const float* bias = (const float*)d_in[5];
    float* out = (float*)d_out;

    k_cw<<<32 + (E_IN + 255) / 256, 256>>>(ei, W);   // W split + degree count
    k_ss<<<1, 1024>>>(ei);                            // scan + scatter
    k_gemm<<<RN / 64, 256>>>(x, attS, attD);
    k_ew<<<(R_TOT * E_MAX + 255) / 256, 256>>>();     // per-edge head weights
    k_agg<<<RN / 8, 256>>>(bias, out);
}

// round 12
// speedup vs baseline: 1.1041x; 1.1041x over previous
#include <cuda_runtime.h>
#include <cuda_fp16.h>
#include <cstdint>

#define R_TOT   48
#define N_NODES 1000
#define RN      48000          // R_TOT * N_NODES
#define E_IN    12000
#define F_DIM   64
#define HC      256            // H * C
#define H_HEADS 4
#define E_MAX   (E_IN + N_NODES)

// ---------------- scratch (static device globals; no allocation) -------------
// h stored as fp16, row-major [RN][256] halves (viewed as [RN][32] uint4 by k_agg)
__device__ uint4  g_hv[(size_t)RN * 32];
__device__ float  g_asrc[RN * H_HEADS];
__device__ float  g_adst[RN * H_HEADS];
__device__ float4 g_Wf[8 * 32 * 32];    // pre-split W fragments: [kstep][ntile][lane]
__device__ int    g_cnt[N_NODES];       // zero-init (BSS); re-zeroed by k_ss
__device__ int    g_rowptr[N_NODES + 1];
__device__ int    g_cursor[N_NODES];
__device__ int    g_csrc[E_MAX];
__device__ int    g_is32;

// ---------------- tf32 helpers ------------------------------------------------
__device__ __forceinline__ unsigned tf32_rna(float v) {
    unsigned r;
    asm("cvt.rna.tf32.f32 %0, %1;" : "=r"(r) : "f"(v));
    return r;
}

#define MMA_TF32(d, a, b0, b1)                                                  \
    asm volatile("mma.sync.aligned.m16n8k8.row.col.f32.tf32.tf32.f32 "          \
                 "{%0,%1,%2,%3}, {%4,%5,%6,%7}, {%8,%9}, {%0,%1,%2,%3};"        \
                 : "+f"((d)[0]), "+f"((d)[1]), "+f"((d)[2]), "+f"((d)[3])       \
                 : "r"((a)[0]), "r"((a)[1]), "r"((a)[2]), "r"((a)[3]),          \
                   "r"(b0), "r"(b1))

// ---------------- CSR build + W split -----------------------------------------
// Original self-loops dropped (reference masks them to -inf => exp == 0 exactly);
// one added self-loop per node occupies the first CSR slot deterministically.

// Width detect by sampling: if edge_index is int64 (values < 1000), EVERY odd
// 32-bit word is zero. 32 sampled odd words all zero on int32 random data has
// probability ~1e-96. Sampled positions stay within the first 24000 words.
__device__ __forceinline__ int detect_is32_warp(const int* e32, int lane) {
    int f = (e32[2 * (lane * 375) + 1] != 0);
    unsigned b = __ballot_sync(0xffffffffu, f);
    return b != 0;
}

// Fused: blocks [0,32) pre-split W into mma B-fragment order; blocks [32,79)
// count edge in-degrees. Independent jobs, one launch.
// B fragment (m16n8k8 .col): lane l: b0 = W[k0 + l%4][n0 + l/4],
//                                     b1 = W[k0 + l%4 + 4][n0 + l/4].
__global__ __launch_bounds__(256) void k_cw(const void* __restrict__ ei,
                                            const float* __restrict__ W) {
    int t = threadIdx.x;
    if (blockIdx.x < 32) {
        int i = blockIdx.x * 256 + t;            // 0..8191
        int lane = i & 31, ntg = (i >> 5) & 31, ks = i >> 10;
        int t4 = lane & 3, g = lane >> 2;
        int col = ntg * 8 + g;
        float b0 = W[(ks * 8 + t4) * HC + col];
        float b1 = W[(ks * 8 + t4 + 4) * HC + col];
        unsigned b0h = tf32_rna(b0), b1h = tf32_rna(b1);
        unsigned b0l = tf32_rna(b0 - __uint_as_float(b0h));
        unsigned b1l = tf32_rna(b1 - __uint_as_float(b1h));
        g_Wf[i] = make_float4(__uint_as_float(b0h), __uint_as_float(b1h),
                              __uint_as_float(b0l), __uint_as_float(b1l));
        return;
    }
    __shared__ int s_is32;
    const int* e32 = (const int*)ei;
    const long long* e64 = (const long long*)ei;
    if (t < 32) {
        int is32 = detect_is32_warp(e32, t);
        if (t == 0) {
            s_is32 = is32;
            if (blockIdx.x == 32) g_is32 = is32;
        }
    }
    __syncthreads();
    int is32 = s_is32;
    int e = (blockIdx.x - 32) * 256 + t;
    if (e < E_IN) {
        int s = is32 ? e32[e] : (int)e64[e];
        int d = is32 ? e32[E_IN + e] : (int)e64[E_IN + e];
        if (s != d) atomicAdd(&g_cnt[d], 1);   // spread over 1000 L2 addresses
    }
}

// Fused scan + scatter: one block, 1024 threads. Scan builds rowptr/cursor,
// scatter register-batches 12 edges/thread and places them via global atomics
// (spread over 1000 L2 addresses). g_cnt re-zeroed for graph replay.
__global__ __launch_bounds__(1024) void k_ss(const void* __restrict__ ei) {
    __shared__ int s_wsum[32];
    int t = threadIdx.x, lane = t & 31, wid = t >> 5;
    int v = (t < N_NODES) ? (g_cnt[t] + 1) : 0;      // +1 = added self-loop
    int x = v;
#pragma unroll
    for (int o = 1; o < 32; o <<= 1) {
        int y = __shfl_up_sync(0xffffffffu, x, o);
        if (lane >= o) x += y;
    }
    if (lane == 31) s_wsum[wid] = x;
    __syncthreads();
    if (wid == 0) {
        int w = s_wsum[lane];
#pragma unroll
        for (int o = 1; o < 32; o <<= 1) {
            int y = __shfl_up_sync(0xffffffffu, w, o);
            if (lane >= o) w += y;
        }
        s_wsum[lane] = w;
    }
    __syncthreads();
    int incl = x + (wid ? s_wsum[wid - 1] : 0);
    int excl = incl - v;
    if (t < N_NODES) {
        g_rowptr[t] = excl;
        g_csrc[excl] = t;                // self-loop first, deterministic
        g_cursor[t] = excl + 1;
        g_cnt[t] = 0;                    // reset for next graph replay
    }
    if (t == N_NODES - 1) g_rowptr[N_NODES] = incl;

    // batch-load edges into registers (MLP) while scan settles
    const int* e32 = (const int*)ei;
    const long long* e64 = (const long long*)ei;
    int is32 = g_is32;
    int sv[12], dv[12];
    if (is32) {
#pragma unroll
        for (int k = 0; k < 12; k++) {
            int e = t + k * 1024;
            sv[k] = (e < E_IN) ? e32[e] : 0;
            dv[k] = (e < E_IN) ? e32[E_IN + e] : 0;
        }
    } else {
#pragma unroll
        for (int k = 0; k < 12; k++) {
            int e = t + k * 1024;
            sv[k] = (e < E_IN) ? (int)e64[e] : 0;
            dv[k] = (e < E_IN) ? (int)e64[E_IN + e] : 0;
        }
    }
    __syncthreads();                     // cursor writes visible to atomics
#pragma unroll
    for (int k = 0; k < 12; k++) {
        int e = t + k * 1024;
        if (e < E_IN && sv[k] != dv[k]) {
            int p = atomicAdd(&g_cursor[dv[k]], 1);
            g_csrc[p] = sv[k];
        }
    }
}

// ---------------- projection GEMM (tensor cores, 3xTF32) + logits -------------
// Best-measured gemm variant (R8): scalar x loads + in-loop hi/lo split.
// Block: 8 warps = 2 row-groups x 4 col-groups; warp = 32 rows x 64 cols
// (one head per warp -> logits close with a 4-lane quad reduction).
// D = Xhi*Whi + Xhi*Wlo + Xlo*Whi (fp32 accum): error ~1e-7.
__global__ __launch_bounds__(256, 2) void k_gemm(const float* __restrict__ x,
                                                 const float* __restrict__ attS,
                                                 const float* __restrict__ attD) {
    __shared__ float sAS[HC], sAD[HC];
    int t = threadIdx.x, warp = t >> 5, lane = t & 31;
    int g = lane >> 2, t4 = lane & 3;
    int mg = warp >> 2, ng = warp & 3;
    int rbase = blockIdx.x * 64 + mg * 32;

    if (t < HC) { sAS[t] = attS[t]; sAD[t] = attD[t]; }
    __syncthreads();

    float acc[2][8][4];
#pragma unroll
    for (int mt = 0; mt < 2; mt++)
#pragma unroll
        for (int nt = 0; nt < 8; nt++)
#pragma unroll
            for (int j = 0; j < 4; j++) acc[mt][nt][j] = 0.f;

#pragma unroll
    for (int ks = 0; ks < 8; ks++) {
        unsigned ah[2][4], al[2][4];
#pragma unroll
        for (int mt = 0; mt < 2; mt++) {
            const float* xp = x + (size_t)(rbase + mt * 16 + g) * F_DIM + ks * 8 + t4;
            float v0 = xp[0];            // (row g,    col t4)
            float v1 = xp[8 * F_DIM];    // (row g+8,  col t4)
            float v2 = xp[4];            // (row g,    col t4+4)
            float v3 = xp[8 * F_DIM + 4];
            ah[mt][0] = tf32_rna(v0); al[mt][0] = tf32_rna(v0 - __uint_as_float(ah[mt][0]));
            ah[mt][1] = tf32_rna(v1); al[mt][1] = tf32_rna(v1 - __uint_as_float(ah[mt][1]));
            ah[mt][2] = tf32_rna(v2); al[mt][2] = tf32_rna(v2 - __uint_as_float(ah[mt][2]));
            ah[mt][3] = tf32_rna(v3); al[mt][3] = tf32_rna(v3 - __uint_as_float(ah[mt][3]));
        }
#pragma unroll
        for (int nt = 0; nt < 8; nt++) {
            float4 b = g_Wf[((size_t)ks * 32 + ng * 8 + nt) * 32 + lane];  // LDG.128
            unsigned b0h = __float_as_uint(b.x), b1h = __float_as_uint(b.y);
            unsigned b0l = __float_as_uint(b.z), b1l = __float_as_uint(b.w);
#pragma unroll
            for (int mt = 0; mt < 2; mt++) {
                MMA_TF32(acc[mt][nt], ah[mt], b0h, b1h);
                MMA_TF32(acc[mt][nt], ah[mt], b0l, b1l);
                MMA_TF32(acc[mt][nt], al[mt], b0h, b1h);
            }
        }
    }

    // epilogue: logits (this warp's head = ng) + fp16 h store
    int head = ng, n0 = ng * 64;
    __half* hbase = (__half*)g_hv;
#pragma unroll
    for (int mt = 0; mt < 2; mt++) {
        int row0 = rbase + mt * 16 + g;          // and row0 + 8
        float as0 = 0.f, ad0 = 0.f, as1 = 0.f, ad1 = 0.f;
#pragma unroll
        for (int nt = 0; nt < 8; nt++) {
            int c = n0 + nt * 8 + 2 * t4;
            float* a = acc[mt][nt];
            as0 += a[0] * sAS[c] + a[1] * sAS[c + 1];
            ad0 += a[0] * sAD[c] + a[1] * sAD[c + 1];
            as1 += a[2] * sAS[c] + a[3] * sAS[c + 1];
            ad1 += a[2] * sAD[c] + a[3] * sAD[c + 1];
            *(__half2*)(hbase + (size_t)row0 * HC + c)       = __floats2half2_rn(a[0], a[1]);
            *(__half2*)(hbase + (size_t)(row0 + 8) * HC + c) = __floats2half2_rn(a[2], a[3]);
        }
        // quad reduce over t4 (lanes xor 1, 2)
        as0 += __shfl_xor_sync(0xffffffffu, as0, 1); as0 += __shfl_xor_sync(0xffffffffu, as0, 2);
        ad0 += __shfl_xor_sync(0xffffffffu, ad0, 1); ad0 += __shfl_xor_sync(0xffffffffu, ad0, 2);
        as1 += __shfl_xor_sync(0xffffffffu, as1, 1); as1 += __shfl_xor_sync(0xffffffffu, as1, 2);
        ad1 += __shfl_xor_sync(0xffffffffu, ad1, 1); ad1 += __shfl_xor_sync(0xffffffffu, ad1, 2);
        if (t4 == 0) {
            g_asrc[row0 * 4 + head] = as0;
            g_adst[row0 * 4 + head] = ad0;
            g_asrc[(row0 + 8) * 4 + head] = as1;
            g_adst[(row0 + 8) * 4 + head] = ad1;
        }
    }
}

// ---------------- softmax aggregation (single pass, one warp per (r, dst)) ----
// Best-measured agg variant (R8/R10). No max-shift: logits bounded far below 80,
// so exp(e) equals the reference's shifted softmax; den eps 1e-16 matches ref.
__global__ __launch_bounds__(256) void k_agg(const float* __restrict__ bias,
                                             float* __restrict__ out) {
    int gw = (blockIdx.x * blockDim.x + threadIdx.x) >> 5;
    int lane = threadIdx.x & 31;
    if (gw >= RN) return;
    int r = gw / N_NODES, i = gw - r * N_NODES;
    int head = lane >> 3;
    int start = g_rowptr[i], end = g_rowptr[i + 1];
    int rbase = r * N_NODES;

    float adsth = g_adst[(rbase + i) * 4 + head];

    float den = 1e-16f;
    float a0 = 0.f, a1 = 0.f, a2 = 0.f, a3 = 0.f;
    float a4 = 0.f, a5 = 0.f, a6 = 0.f, a7 = 0.f;

#pragma unroll 2
    for (int k = start; k < end; k++) {
        int s = g_csrc[k];
        float e = g_asrc[(rbase + s) * 4 + head] + adsth;
        e = (e > 0.f) ? e : 0.2f * e;
        float w = __expf(fminf(e, 80.f));
        den += w;
        uint4 u = g_hv[(size_t)(rbase + s) * 32 + lane];   // 16B/lane, 512B/warp
        float2 f0 = __half22float2(*reinterpret_cast<__half2*>(&u.x));
        float2 f1 = __half22float2(*reinterpret_cast<__half2*>(&u.y));
        float2 f2 = __half22float2(*reinterpret_cast<__half2*>(&u.z));
        float2 f3 = __half22float2(*reinterpret_cast<__half2*>(&u.w));
        a0 += w * f0.x; a1 += w * f0.y; a2 += w * f1.x; a3 += w * f1.y;
        a4 += w * f2.x; a5 += w * f2.y; a6 += w * f3.x; a7 += w * f3.y;
    }

    float inv = 1.0f / den;
    float a[8] = {a0 * inv, a1 * inv, a2 * inv, a3 * inv,
                  a4 * inv, a5 * inv, a6 * inv, a7 * inv};

    // head mean: lanes l, l^8, l^16, l^24 hold same channel, different heads
#pragma unroll
    for (int k = 0; k < 8; k++) {
        a[k] += __shfl_xor_sync(0xffffffffu, a[k], 8);
        a[k] += __shfl_xor_sync(0xffffffffu, a[k], 16);
    }

    if (lane < 8) {
        const float4* bp = (const float4*)bias;
        float4 b0 = bp[lane * 2], b1 = bp[lane * 2 + 1];
        float4 o0 = make_float4(0.25f * a[0] + b0.x, 0.25f * a[1] + b0.y,
                                0.25f * a[2] + b0.z, 0.25f * a[3] + b0.w);
        float4 o1 = make_float4(0.25f * a[4] + b1.x, 0.25f * a[5] + b1.y,
                                0.25f * a[6] + b1.z, 0.25f * a[7] + b1.w);
        float4* op = (float4*)(out + (size_t)(rbase + i) * 64 + lane * 8);
        op[0] = o0;
        op[1] = o1;
    }
}

// ---------------- launch ------------------------------------------------------
extern "C" void kernel_launch(void* const* d_in, const int* in_sizes, int n_in,
                              void* d_out, int out_size) {
    const float* x    = (const float*)d_in[0];
    const void*  ei   = d_in[1];
    const float* W    = (const float*)d_in[2];
    const float* attS = (const float*)d_in[3];
    const float* attD = (const float*)d_in[4];
    const float* bias = (const float*)d_in[5];
    float* out = (float*)d_out;

    k_cw<<<32 + (E_IN + 255) / 256, 256>>>(ei, W);   // W split + degree count
    k_ss<<<1, 1024>>>(ei);                            // scan + scatter
    k_gemm<<<RN / 64, 256>>>(x, attS, attD);
    k_agg<<<RN / 8, 256>>>(bias, out);
}

// round 13
// speedup vs baseline: 1.1063x; 1.0020x over previous
#include <cuda_runtime.h>
#include <cuda_fp16.h>
#include <cstdint>

#define R_TOT   48
#define N_NODES 1000
#define RN      48000          // R_TOT * N_NODES
#define E_IN    12000
#define F_DIM   64
#define HC      256            // H * C
#define H_HEADS 4
#define E_MAX   (E_IN + N_NODES)

// ---------------- scratch (static device globals; no allocation) -------------
// h stored as fp16, row-major [RN][256] halves (viewed as [RN][32] uint4 by k_agg)
__device__ uint4  g_hv[(size_t)RN * 32];
__device__ float  g_asrc[RN * H_HEADS];
__device__ float  g_adst[RN * H_HEADS];
__device__ float4 g_Wf[8 * 32 * 32];    // pre-split W fragments: [kstep][ntile][lane]
__device__ int    g_cnt[N_NODES];       // zero-init (BSS); re-zeroed by k_ss
__device__ int    g_rowptr[N_NODES + 1];
__device__ int    g_cursor[N_NODES];
__device__ int    g_csrc[E_MAX];
__device__ int    g_is32;

// ---------------- packed / tf32 helpers ---------------------------------------
union F2U { unsigned long long u; float2 f; };
__device__ __forceinline__ unsigned long long fma2(unsigned long long a,
                                                   unsigned long long b,
                                                   unsigned long long c) {
    unsigned long long d;
    asm("fma.rn.f32x2 %0, %1, %2, %3;" : "=l"(d) : "l"(a), "l"(b), "l"(c));
    return d;
}

__device__ __forceinline__ unsigned tf32_rna(float v) {
    unsigned r;
    asm("cvt.rna.tf32.f32 %0, %1;" : "=r"(r) : "f"(v));
    return r;
}

#define MMA_TF32(d, a, b0, b1)                                                  \
    asm volatile("mma.sync.aligned.m16n8k8.row.col.f32.tf32.tf32.f32 "          \
                 "{%0,%1,%2,%3}, {%4,%5,%6,%7}, {%8,%9}, {%0,%1,%2,%3};"        \
                 : "+f"((d)[0]), "+f"((d)[1]), "+f"((d)[2]), "+f"((d)[3])       \
                 : "r"((a)[0]), "r"((a)[1]), "r"((a)[2]), "r"((a)[3]),          \
                   "r"(b0), "r"(b1))

// ---------------- CSR build + W split -----------------------------------------
// Original self-loops dropped (reference masks them to -inf => exp == 0 exactly);
// one added self-loop per node occupies the first CSR slot deterministically.

// Width detect by sampling: if edge_index is int64 (values < 1000), EVERY odd
// 32-bit word is zero. 32 sampled odd words all zero on int32 random data has
// probability ~1e-96. Sampled positions stay within the first 24000 words.
__device__ __forceinline__ int detect_is32_warp(const int* e32, int lane) {
    int f = (e32[2 * (lane * 375) + 1] != 0);
    unsigned b = __ballot_sync(0xffffffffu, f);
    return b != 0;
}

// Fused: blocks [0,32) pre-split W into mma B-fragment order; blocks [32,79)
// count edge in-degrees. Independent jobs, one launch.
__global__ __launch_bounds__(256) void k_cw(const void* __restrict__ ei,
                                            const float* __restrict__ W) {
    int t = threadIdx.x;
    if (blockIdx.x < 32) {
        int i = blockIdx.x * 256 + t;            // 0..8191
        int lane = i & 31, ntg = (i >> 5) & 31, ks = i >> 10;
        int t4 = lane & 3, g = lane >> 2;
        int col = ntg * 8 + g;
        float b0 = W[(ks * 8 + t4) * HC + col];
        float b1 = W[(ks * 8 + t4 + 4) * HC + col];
        unsigned b0h = tf32_rna(b0), b1h = tf32_rna(b1);
        unsigned b0l = tf32_rna(b0 - __uint_as_float(b0h));
        unsigned b1l = tf32_rna(b1 - __uint_as_float(b1h));
        g_Wf[i] = make_float4(__uint_as_float(b0h), __uint_as_float(b1h),
                              __uint_as_float(b0l), __uint_as_float(b1l));
        return;
    }
    __shared__ int s_is32;
    const int* e32 = (const int*)ei;
    const long long* e64 = (const long long*)ei;
    if (t < 32) {
        int is32 = detect_is32_warp(e32, t);
        if (t == 0) {
            s_is32 = is32;
            if (blockIdx.x == 32) g_is32 = is32;
        }
    }
    __syncthreads();
    int is32 = s_is32;
    int e = (blockIdx.x - 32) * 256 + t;
    if (e < E_IN) {
        int s = is32 ? e32[e] : (int)e64[e];
        int d = is32 ? e32[E_IN + e] : (int)e64[E_IN + e];
        if (s != d) atomicAdd(&g_cnt[d], 1);   // spread over 1000 L2 addresses
    }
}

// Fused scan + scatter: one block, 1024 threads.
__global__ __launch_bounds__(1024) void k_ss(const void* __restrict__ ei) {
    __shared__ int s_wsum[32];
    int t = threadIdx.x, lane = t & 31, wid = t >> 5;
    int v = (t < N_NODES) ? (g_cnt[t] + 1) : 0;      // +1 = added self-loop
    int x = v;
#pragma unroll
    for (int o = 1; o < 32; o <<= 1) {
        int y = __shfl_up_sync(0xffffffffu, x, o);
        if (lane >= o) x += y;
    }
    if (lane == 31) s_wsum[wid] = x;
    __syncthreads();
    if (wid == 0) {
        int w = s_wsum[lane];
#pragma unroll
        for (int o = 1; o < 32; o <<= 1) {
            int y = __shfl_up_sync(0xffffffffu, w, o);
            if (lane >= o) w += y;
        }
        s_wsum[lane] = w;
    }
    __syncthreads();
    int incl = x + (wid ? s_wsum[wid - 1] : 0);
    int excl = incl - v;
    if (t < N_NODES) {
        g_rowptr[t] = excl;
        g_csrc[excl] = t;                // self-loop first, deterministic
        g_cursor[t] = excl + 1;
        g_cnt[t] = 0;                    // reset for next graph replay
    }
    if (t == N_NODES - 1) g_rowptr[N_NODES] = incl;

    const int* e32 = (const int*)ei;
    const long long* e64 = (const long long*)ei;
    int is32 = g_is32;
    int sv[12], dv[12];
    if (is32) {
#pragma unroll
        for (int k = 0; k < 12; k++) {
            int e = t + k * 1024;
            sv[k] = (e < E_IN) ? e32[e] : 0;
            dv[k] = (e < E_IN) ? e32[E_IN + e] : 0;
        }
    } else {
#pragma unroll
        for (int k = 0; k < 12; k++) {
            int e = t + k * 1024;
            sv[k] = (e < E_IN) ? (int)e64[e] : 0;
            dv[k] = (e < E_IN) ? (int)e64[E_IN + e] : 0;
        }
    }
    __syncthreads();
#pragma unroll
    for (int k = 0; k < 12; k++) {
        int e = t + k * 1024;
        if (e < E_IN && sv[k] != dv[k]) {
            int p = atomicAdd(&g_cursor[dv[k]], 1);
            g_csrc[p] = sv[k];
        }
    }
}

// ---------------- projection GEMM (tensor cores, 3xTF32) + logits -------------
// Occupancy-oriented variant: warp tile 16 rows x 64 cols (ONE m16 tile ->
// acc 32 regs), __launch_bounds__(256,4) -> 32 warps/SM (2x latency hiding).
// Block: 8 warps = 2 row-groups x 4 col-groups; block tile 32 rows; grid 1500.
// One head per warp -> logits close with a 4-lane quad reduction.
// D = Xhi*Whi + Xhi*Wlo + Xlo*Whi (fp32 accum): error ~1e-7.
__global__ __launch_bounds__(256, 4) void k_gemm(const float* __restrict__ x,
                                                 const float* __restrict__ attS,
                                                 const float* __restrict__ attD) {
    __shared__ float sAS[HC], sAD[HC];
    int t = threadIdx.x, warp = t >> 5, lane = t & 31;
    int g = lane >> 2, t4 = lane & 3;
    int mg = warp >> 2, ng = warp & 3;
    int rbase = blockIdx.x * 32 + mg * 16;

    if (t < HC) { sAS[t] = attS[t]; sAD[t] = attD[t]; }
    __syncthreads();

    float acc[8][4];
#pragma unroll
    for (int nt = 0; nt < 8; nt++)
#pragma unroll
        for (int j = 0; j < 4; j++) acc[nt][j] = 0.f;

#pragma unroll
    for (int ks = 0; ks < 8; ks++) {
        unsigned ah[4], al[4];
        {
            const float* xp = x + (size_t)(rbase + g) * F_DIM + ks * 8 + t4;
            float v0 = xp[0];            // (row g,    col t4)
            float v1 = xp[8 * F_DIM];    // (row g+8,  col t4)
            float v2 = xp[4];            // (row g,    col t4+4)
            float v3 = xp[8 * F_DIM + 4];
            ah[0] = tf32_rna(v0); al[0] = tf32_rna(v0 - __uint_as_float(ah[0]));
            ah[1] = tf32_rna(v1); al[1] = tf32_rna(v1 - __uint_as_float(ah[1]));
            ah[2] = tf32_rna(v2); al[2] = tf32_rna(v2 - __uint_as_float(ah[2]));
            ah[3] = tf32_rna(v3); al[3] = tf32_rna(v3 - __uint_as_float(ah[3]));
        }
#pragma unroll
        for (int nt = 0; nt < 8; nt++) {
            float4 b = g_Wf[((size_t)ks * 32 + ng * 8 + nt) * 32 + lane];  // LDG.128
            unsigned b0h = __float_as_uint(b.x), b1h = __float_as_uint(b.y);
            unsigned b0l = __float_as_uint(b.z), b1l = __float_as_uint(b.w);
            MMA_TF32(acc[nt], ah, b0h, b1h);
            MMA_TF32(acc[nt], ah, b0l, b1l);
            MMA_TF32(acc[nt], al, b0h, b1h);
        }
    }

    // epilogue: logits (this warp's head = ng) + fp16 h store
    int head = ng, n0 = ng * 64;
    __half* hbase = (__half*)g_hv;
    {
        int row0 = rbase + g;                    // and row0 + 8
        float as0 = 0.f, ad0 = 0.f, as1 = 0.f, ad1 = 0.f;
#pragma unroll
        for (int nt = 0; nt < 8; nt++) {
            int c = n0 + nt * 8 + 2 * t4;
            float* a = acc[nt];
            as0 += a[0] * sAS[c] + a[1] * sAS[c + 1];
            ad0 += a[0] * sAD[c] + a[1] * sAD[c + 1];
            as1 += a[2] * sAS[c] + a[3] * sAS[c + 1];
            ad1 += a[2] * sAD[c] + a[3] * sAD[c + 1];
            *(__half2*)(hbase + (size_t)row0 * HC + c)       = __floats2half2_rn(a[0], a[1]);
            *(__half2*)(hbase + (size_t)(row0 + 8) * HC + c) = __floats2half2_rn(a[2], a[3]);
        }
        // quad reduce over t4 (lanes xor 1, 2)
        as0 += __shfl_xor_sync(0xffffffffu, as0, 1); as0 += __shfl_xor_sync(0xffffffffu, as0, 2);
        ad0 += __shfl_xor_sync(0xffffffffu, ad0, 1); ad0 += __shfl_xor_sync(0xffffffffu, ad0, 2);
        as1 += __shfl_xor_sync(0xffffffffu, as1, 1); as1 += __shfl_xor_sync(0xffffffffu, as1, 2);
        ad1 += __shfl_xor_sync(0xffffffffu, ad1, 1); ad1 += __shfl_xor_sync(0xffffffffu, ad1, 2);
        if (t4 == 0) {
            g_asrc[row0 * 4 + head] = as0;
            g_adst[row0 * 4 + head] = ad0;
            g_asrc[(row0 + 8) * 4 + head] = as1;
            g_adst[(row0 + 8) * 4 + head] = ad1;
        }
    }
}

// ---------------- softmax aggregation (single pass, one warp per (r, dst)) ----
// R8 structure with packed fma2 accumulate (4 fma2 replace 8 FFMA).
// No max-shift: logits bounded far below 80, so exp(e) equals the reference's
// shifted softmax; den eps 1e-16 matches ref.
__global__ __launch_bounds__(256) void k_agg(const float* __restrict__ bias,
                                             float* __restrict__ out) {
    int gw = (blockIdx.x * blockDim.x + threadIdx.x) >> 5;
    int lane = threadIdx.x & 31;
    if (gw >= RN) return;
    int r = gw / N_NODES, i = gw - r * N_NODES;
    int head = lane >> 3;
    int start = g_rowptr[i], end = g_rowptr[i + 1];
    int rbase = r * N_NODES;
    const float* asrcp = g_asrc + (size_t)rbase * 4 + head;
    const uint4* hvp = g_hv + (size_t)rbase * 32 + lane;

    float adsth = g_adst[(rbase + i) * 4 + head];

    float den = 1e-16f;
    unsigned long long acc[4] = {0ULL, 0ULL, 0ULL, 0ULL};

#pragma unroll 2
    for (int k = start; k < end; k++) {
        int s = g_csrc[k];
        float e = asrcp[s * 4] + adsth;
        e = (e > 0.f) ? e : 0.2f * e;
        float w = __expf(fminf(e, 80.f));
        den += w;
        F2U wp; wp.f = make_float2(w, w);
        uint4 u = hvp[(size_t)s * 32];           // 16B/lane, 512B/warp
        F2U f0, f1, f2, f3;
        f0.f = __half22float2(*reinterpret_cast<__half2*>(&u.x));
        f1.f = __half22float2(*reinterpret_cast<__half2*>(&u.y));
        f2.f = __half22float2(*reinterpret_cast<__half2*>(&u.z));
        f3.f = __half22float2(*reinterpret_cast<__half2*>(&u.w));
        acc[0] = fma2(wp.u, f0.u, acc[0]);
        acc[1] = fma2(wp.u, f1.u, acc[1]);
        acc[2] = fma2(wp.u, f2.u, acc[2]);
        acc[3] = fma2(wp.u, f3.u, acc[3]);
    }

    float inv = 1.0f / den;
    float a[8];
#pragma unroll
    for (int j = 0; j < 4; j++) {
        F2U u; u.u = acc[j];
        a[2 * j] = u.f.x * inv; a[2 * j + 1] = u.f.y * inv;
    }

    // head mean: lanes l, l^8, l^16, l^24 hold same channel, different heads
#pragma unroll
    for (int k = 0; k < 8; k++) {
        a[k] += __shfl_xor_sync(0xffffffffu, a[k], 8);
        a[k] += __shfl_xor_sync(0xffffffffu, a[k], 16);
    }

    if (lane < 8) {
        const float4* bp = (const float4*)bias;
        float4 b0 = bp[lane * 2], b1 = bp[lane * 2 + 1];
        float4 o0 = make_float4(0.25f * a[0] + b0.x, 0.25f * a[1] + b0.y,
                                0.25f * a[2] + b0.z, 0.25f * a[3] + b0.w);
        float4 o1 = make_float4(0.25f * a[4] + b1.x, 0.25f * a[5] + b1.y,
                                0.25f * a[6] + b1.z, 0.25f * a[7] + b1.w);
        float4* op = (float4*)(out + (size_t)(rbase + i) * 64 + lane * 8);
        op[0] = o0;
        op[1] = o1;
    }
}

// ---------------- launch ------------------------------------------------------
extern "C" void kernel_launch(void* const* d_in, const int* in_sizes, int n_in,
                              void* d_out, int out_size) {
    const float* x    = (const float*)d_in[0];
    const void*  ei   = d_in[1];
    const float* W    = (const float*)d_in[2];
    const float* attS = (const float*)d_in[3];
    const float* attD = (const float*)d_in[4];
    const float* bias = (const float*)d_in[5];
    float* out = (float*)d_out;

    k_cw<<<32 + (E_IN + 255) / 256, 256>>>(ei, W);   // W split + degree count
    k_ss<<<1, 1024>>>(ei);                            // scan + scatter
    k_gemm<<<RN / 32, 256>>>(x, attS, attD);
    k_agg<<<RN / 8, 256>>>(bias, out);
}

// round 14
// speedup vs baseline: 1.2687x; 1.1467x over previous
#include <cuda_runtime.h>
#include <cuda_fp16.h>
#include <cstdint>

#define R_TOT   48
#define N_NODES 1000
#define RN      48000          // R_TOT * N_NODES
#define E_IN    12000
#define F_DIM   64
#define HC      256            // H * C
#define H_HEADS 4
#define BKT     96             // bucket capacity: mean deg 12, 24 sigma margin

// ---------------- scratch (static device globals; no allocation) -------------
// h stored as fp16, row-major [RN][256] halves (viewed as [RN][32] uint4 by k_agg)
__device__ uint4  g_hv[(size_t)RN * 32];
__device__ float  g_asrc[RN * H_HEADS];
__device__ float  g_adst[RN * H_HEADS];
__device__ float4 g_Wf[8 * 32 * 32];    // pre-split W fragments: [kstep][ntile][lane]
__device__ int    g_cursor[N_NODES];    // bucket fill count (init 1 by k_prep)
__device__ int    g_bkt[N_NODES * BKT]; // incoming-edge sources per node
__device__ int    g_is32;

// ---------------- packed / tf32 helpers ---------------------------------------
union F2U { unsigned long long u; float2 f; };
__device__ __forceinline__ unsigned long long fma2(unsigned long long a,
                                                   unsigned long long b,
                                                   unsigned long long c) {
    unsigned long long d;
    asm("fma.rn.f32x2 %0, %1, %2, %3;" : "=l"(d) : "l"(a), "l"(b), "l"(c));
    return d;
}

__device__ __forceinline__ unsigned tf32_rna(float v) {
    unsigned r;
    asm("cvt.rna.tf32.f32 %0, %1;" : "=r"(r) : "f"(v));
    return r;
}

#define MMA_TF32(d, a, b0, b1)                                                  \
    asm volatile("mma.sync.aligned.m16n8k8.row.col.f32.tf32.tf32.f32 "          \
                 "{%0,%1,%2,%3}, {%4,%5,%6,%7}, {%8,%9}, {%0,%1,%2,%3};"        \
                 : "+f"((d)[0]), "+f"((d)[1]), "+f"((d)[2]), "+f"((d)[3])       \
                 : "r"((a)[0]), "r"((a)[1]), "r"((a)[2]), "r"((a)[3]),          \
                   "r"(b0), "r"(b1))

// ---------------- prep: W split + bucket init ----------------------------------
// Blocks [0,32): pre-split W into mma B-fragment order.
// Blocks [32,36): per-node cursor=1 and self-loop in slot 0 (deterministic).
// Original self-loops are dropped (reference masks them to -inf => exp == 0).
__global__ __launch_bounds__(256) void k_prep(const float* __restrict__ W) {
    int t = threadIdx.x;
    if (blockIdx.x < 32) {
        int i = blockIdx.x * 256 + t;            // 0..8191
        int lane = i & 31, ntg = (i >> 5) & 31, ks = i >> 10;
        int t4 = lane & 3, g = lane >> 2;
        int col = ntg * 8 + g;
        float b0 = W[(ks * 8 + t4) * HC + col];
        float b1 = W[(ks * 8 + t4 + 4) * HC + col];
        unsigned b0h = tf32_rna(b0), b1h = tf32_rna(b1);
        unsigned b0l = tf32_rna(b0 - __uint_as_float(b0h));
        unsigned b1l = tf32_rna(b1 - __uint_as_float(b1h));
        g_Wf[i] = make_float4(__uint_as_float(b0h), __uint_as_float(b1h),
                              __uint_as_float(b0l), __uint_as_float(b1l));
        return;
    }
    int i = (blockIdx.x - 32) * 256 + t;
    if (i < N_NODES) {
        g_cursor[i] = 1;
        g_bkt[i * BKT] = i;              // added self-loop, slot 0
    }
}

// Width detect by sampling: if edge_index is int64 (values < 1000), EVERY odd
// 32-bit word is zero. 32 sampled odd words all zero on int32 random data has
// probability ~1e-96. Sampled positions stay within the first 24000 words.
__device__ __forceinline__ int detect_is32_warp(const int* e32, int lane) {
    int f = (e32[2 * (lane * 375) + 1] != 0);
    unsigned b = __ballot_sync(0xffffffffu, f);
    return b != 0;
}

// Single-pass bucketed scatter: p = atomicAdd(cursor[d]); bkt[d*BKT+p] = s.
__global__ __launch_bounds__(256) void k_scatter(const void* __restrict__ ei) {
    __shared__ int s_is32;
    const int* e32 = (const int*)ei;
    const long long* e64 = (const long long*)ei;
    int t = threadIdx.x;
    if (t < 32) {
        int is32 = detect_is32_warp(e32, t);
        if (t == 0) s_is32 = is32;
    }
    __syncthreads();
    int is32 = s_is32;
    int e = blockIdx.x * 256 + t;
    if (e < E_IN) {
        int s = is32 ? e32[e] : (int)e64[e];
        int d = is32 ? e32[E_IN + e] : (int)e64[E_IN + e];
        if (s != d) {
            int p = atomicAdd(&g_cursor[d], 1);
            if (p < BKT) g_bkt[d * BKT + p] = s;
        }
    }
}

// ---------------- projection GEMM (tensor cores, 3xTF32) + logits -------------
// Warp tile 16 rows x 64 cols (one m16 tile), 4 blocks/SM, grid 1500.
// A-path: x tile staged in smem (coalesced float4 in, conflict-free LDS.32 out:
// stride 68 -> lane bank = (4g+t4), all 32 distinct). Split hi/lo in-register.
// One head per warp -> logits close with a 4-lane quad reduction.
// D = Xhi*Whi + Xhi*Wlo + Xlo*Whi (fp32 accum): error ~1e-7.
__global__ __launch_bounds__(256, 4) void k_gemm(const float* __restrict__ x,
                                                 const float* __restrict__ attS,
                                                 const float* __restrict__ attD) {
    __shared__ float sX[32 * 68];         // 8.5 KB, rows stride 68 (17x16B)
    __shared__ float sAS[HC], sAD[HC];
    int t = threadIdx.x, warp = t >> 5, lane = t & 31;
    int g = lane >> 2, t4 = lane & 3;
    int mg = warp >> 2, ng = warp & 3;
    int rowBase = blockIdx.x * 32;

    // stage x tile: 32 rows x 16 float4, 2 per thread, coalesced
    for (int i = t; i < 32 * 16; i += 256) {
        int row = i >> 4, j4 = i & 15;
        float4 v = ((const float4*)(x + (size_t)(rowBase + row) * F_DIM))[j4];
        *(float4*)&sX[row * 68 + j4 * 4] = v;
    }
    if (t < HC) { sAS[t] = attS[t]; sAD[t] = attD[t]; }
    __syncthreads();

    float acc[8][4];
#pragma unroll
    for (int nt = 0; nt < 8; nt++)
#pragma unroll
        for (int j = 0; j < 4; j++) acc[nt][j] = 0.f;

    const float* xr0 = sX + (mg * 16 + g) * 68 + t4;

#pragma unroll
    for (int ks = 0; ks < 8; ks++) {
        unsigned ah[4], al[4];
        {
            const float* xr = xr0 + ks * 8;
            float v0 = xr[0];            // (row g,    col t4)
            float v1 = xr[8 * 68];       // (row g+8,  col t4)
            float v2 = xr[4];            // (row g,    col t4+4)
            float v3 = xr[8 * 68 + 4];
            ah[0] = tf32_rna(v0); al[0] = tf32_rna(v0 - __uint_as_float(ah[0]));
            ah[1] = tf32_rna(v1); al[1] = tf32_rna(v1 - __uint_as_float(ah[1]));
            ah[2] = tf32_rna(v2); al[2] = tf32_rna(v2 - __uint_as_float(ah[2]));
            ah[3] = tf32_rna(v3); al[3] = tf32_rna(v3 - __uint_as_float(ah[3]));
        }
#pragma unroll
        for (int nt = 0; nt < 8; nt++) {
            float4 b = g_Wf[((size_t)ks * 32 + ng * 8 + nt) * 32 + lane];  // LDG.128
            unsigned b0h = __float_as_uint(b.x), b1h = __float_as_uint(b.y);
            unsigned b0l = __float_as_uint(b.z), b1l = __float_as_uint(b.w);
            MMA_TF32(acc[nt], ah, b0h, b1h);
            MMA_TF32(acc[nt], ah, b0l, b1l);
            MMA_TF32(acc[nt], al, b0h, b1h);
        }
    }

    // epilogue: logits (this warp's head = ng) + fp16 h store
    int head = ng, n0 = ng * 64;
    __half* hbase = (__half*)g_hv;
    {
        int row0 = rowBase + mg * 16 + g;        // and row0 + 8
        float as0 = 0.f, ad0 = 0.f, as1 = 0.f, ad1 = 0.f;
#pragma unroll
        for (int nt = 0; nt < 8; nt++) {
            int c = n0 + nt * 8 + 2 * t4;
            float* a = acc[nt];
            as0 += a[0] * sAS[c] + a[1] * sAS[c + 1];
            ad0 += a[0] * sAD[c] + a[1] * sAD[c + 1];
            as1 += a[2] * sAS[c] + a[3] * sAS[c + 1];
            ad1 += a[2] * sAD[c] + a[3] * sAD[c + 1];
            *(__half2*)(hbase + (size_t)row0 * HC + c)       = __floats2half2_rn(a[0], a[1]);
            *(__half2*)(hbase + (size_t)(row0 + 8) * HC + c) = __floats2half2_rn(a[2], a[3]);
        }
        // quad reduce over t4 (lanes xor 1, 2)
        as0 += __shfl_xor_sync(0xffffffffu, as0, 1); as0 += __shfl_xor_sync(0xffffffffu, as0, 2);
        ad0 += __shfl_xor_sync(0xffffffffu, ad0, 1); ad0 += __shfl_xor_sync(0xffffffffu, ad0, 2);
        as1 += __shfl_xor_sync(0xffffffffu, as1, 1); as1 += __shfl_xor_sync(0xffffffffu, as1, 2);
        ad1 += __shfl_xor_sync(0xffffffffu, ad1, 1); ad1 += __shfl_xor_sync(0xffffffffu, ad1, 2);
        if (t4 == 0) {
            g_asrc[row0 * 4 + head] = as0;
            g_adst[row0 * 4 + head] = ad0;
            g_asrc[(row0 + 8) * 4 + head] = as1;
            g_adst[(row0 + 8) * 4 + head] = ad1;
        }
    }
}

// ---------------- softmax aggregation (single pass, one warp per (r, dst)) ----
// Best-measured agg (R13): in-loop exp + packed fma2 accumulate; bucket CSR.
// No max-shift: logits bounded far below 80, so exp(e) equals the reference's
// shifted softmax; den eps 1e-16 matches ref.
__global__ __launch_bounds__(256) void k_agg(const float* __restrict__ bias,
                                             float* __restrict__ out) {
    int gw = (blockIdx.x * blockDim.x + threadIdx.x) >> 5;
    int lane = threadIdx.x & 31;
    if (gw >= RN) return;
    int r = gw / N_NODES, i = gw - r * N_NODES;
    int head = lane >> 3;
    int cnt = g_cursor[i];
    const int* bkt = g_bkt + i * BKT;
    int rbase = r * N_NODES;
    const float* asrcp = g_asrc + (size_t)rbase * 4 + head;
    const uint4* hvp = g_hv + (size_t)rbase * 32 + lane;

    float adsth = g_adst[(rbase + i) * 4 + head];

    float den = 1e-16f;
    unsigned long long acc[4] = {0ULL, 0ULL, 0ULL, 0ULL};

#pragma unroll 2
    for (int k = 0; k < cnt; k++) {
        int s = bkt[k];
        float e = asrcp[s * 4] + adsth;
        e = (e > 0.f) ? e : 0.2f * e;
        float w = __expf(fminf(e, 80.f));
        den += w;
        F2U wp; wp.f = make_float2(w, w);
        uint4 u = hvp[(size_t)s * 32];           // 16B/lane, 512B/warp
        F2U f0, f1, f2, f3;
        f0.f = __half22float2(*reinterpret_cast<__half2*>(&u.x));
        f1.f = __half22float2(*reinterpret_cast<__half2*>(&u.y));
        f2.f = __half22float2(*reinterpret_cast<__half2*>(&u.z));
        f3.f = __half22float2(*reinterpret_cast<__half2*>(&u.w));
        acc[0] = fma2(wp.u, f0.u, acc[0]);
        acc[1] = fma2(wp.u, f1.u, acc[1]);
        acc[2] = fma2(wp.u, f2.u, acc[2]);
        acc[3] = fma2(wp.u, f3.u, acc[3]);
    }

    float inv = 1.0f / den;
    float a[8];
#pragma unroll
    for (int j = 0; j < 4; j++) {
        F2U u; u.u = acc[j];
        a[2 * j] = u.f.x * inv; a[2 * j + 1] = u.f.y * inv;
    }

    // head mean: lanes l, l^8, l^16, l^24 hold same channel, different heads
#pragma unroll
    for (int k = 0; k < 8; k++) {
        a[k] += __shfl_xor_sync(0xffffffffu, a[k], 8);
        a[k] += __shfl_xor_sync(0xffffffffu, a[k], 16);
    }

    if (lane < 8) {
        const float4* bp = (const float4*)bias;
        float4 b0 = bp[lane * 2], b1 = bp[lane * 2 + 1];
        float4 o0 = make_float4(0.25f * a[0] + b0.x, 0.25f * a[1] + b0.y,
                                0.25f * a[2] + b0.z, 0.25f * a[3] + b0.w);
        float4 o1 = make_float4(0.25f * a[4] + b1.x, 0.25f * a[5] + b1.y,
                                0.25f * a[6] + b1.z, 0.25f * a[7] + b1.w);
        float4* op = (float4*)(out + (size_t)(rbase + i) * 64 + lane * 8);
        op[0] = o0;
        op[1] = o1;
    }
}

// ---------------- launch ------------------------------------------------------
extern "C" void kernel_launch(void* const* d_in, const int* in_sizes, int n_in,
                              void* d_out, int out_size) {
    const float* x    = (const float*)d_in[0];
    const void*  ei   = d_in[1];
    const float* W    = (const float*)d_in[2];
    const float* attS = (const float*)d_in[3];
    const float* attD = (const float*)d_in[4];
    const float* bias = (const float*)d_in[5];
    float* out = (float*)d_out;

    k_prep<<<36, 256>>>(W);                            // W split + bucket init
    k_scatter<<<(E_IN + 255) / 256, 256>>>(ei);        // bucketed edge scatter
    k_gemm<<<RN / 32, 256>>>(x, attS, attD);
    k_agg<<<RN / 8, 256>>>(bias, out);
}